// round 5
// baseline (speedup 1.0000x reference)
#include <cuda_runtime.h>
#include <math.h>

#define Bb   2
#define Ss   2048
#define Dd   1024
#define Hh   16
#define HDd  64
#define Ff   4096
#define NTOK (Bb*Ss)   // 4096

// ---------------- scratch (device globals: the sanctioned scratch mechanism) ----
__device__ float g_y [NTOK*Dd];                 // LN output (reused both passes)
__device__ float g_q [NTOK*Dd];
__device__ float g_k [NTOK*Dd];
__device__ float g_kt[NTOK*Dd];                 // K transposed per head: [z][d][t]
__device__ float g_v [NTOK*Dd];
__device__ float g_o [NTOK*Dd];                 // attention output (pre-proj)
__device__ float g_h [NTOK*Dd];                 // residual stream after block 1
__device__ float g_a [NTOK*Dd];                 // attention-2 projection output
__device__ float g_t [NTOK*Ff];                 // FFN intermediate
__device__ float g_sc[(size_t)Bb*Hh*Ss*Ss];     // scores, 512MB

// ---------------- helpers -------------------------------------------------------
__device__ __forceinline__ unsigned f2tf(float x){
    unsigned u; asm("cvt.rna.tf32.f32 %0, %1;" : "=r"(u) : "f"(x)); return u;
}
__device__ __forceinline__ float geluf(float x){
    return 0.5f * x * (1.0f + erff(x * 0.70710678118654752f));
}

// ---------------- LayerNorm: one block (256 thr) per 1024-float row -------------
__global__ void ln_kernel(const float* __restrict__ x,
                          const float* __restrict__ gam,
                          const float* __restrict__ bet,
                          float* __restrict__ y)
{
    __shared__ float rs[2][8];
    int row = blockIdx.x, t = threadIdx.x;
    float4 v = ((const float4*)(x + (size_t)row*Dd))[t];
    float s = v.x+v.y+v.z+v.w;
    float q = v.x*v.x+v.y*v.y+v.z*v.z+v.w*v.w;
    #pragma unroll
    for (int o=16;o;o>>=1){ s += __shfl_xor_sync(0xffffffffu,s,o);
                            q += __shfl_xor_sync(0xffffffffu,q,o); }
    if ((t&31)==0){ rs[0][t>>5]=s; rs[1][t>>5]=q; }
    __syncthreads();
    float S=0.f,Q=0.f;
    #pragma unroll
    for (int i=0;i<8;i++){ S+=rs[0][i]; Q+=rs[1][i]; }
    float mu = S*(1.0f/Dd);
    float var = Q*(1.0f/Dd) - mu*mu;
    float rstd = rsqrtf(var + 1e-5f);
    float4 g4 = ((const float4*)gam)[t];
    float4 b4 = ((const float4*)bet)[t];
    float4 o4;
    o4.x = (v.x-mu)*rstd*g4.x + b4.x;
    o4.y = (v.y-mu)*rstd*g4.y + b4.y;
    o4.z = (v.z-mu)*rstd*g4.z + b4.z;
    o4.w = (v.w-mu)*rstd*g4.w + b4.w;
    ((float4*)(y + (size_t)row*Dd))[t] = o4;
}

// ---------------- per-head K transpose: g_kt[z][d][t] = K[(b,t)][h*64+d] --------
__global__ void transpose_k_kernel(const float* __restrict__ K, float* __restrict__ KT)
{
    __shared__ float tile[32][33];
    int z = blockIdx.z, b = z >> 4, h = z & 15;
    int t0 = blockIdx.x*32, d0 = blockIdx.y*32;
    int tx = threadIdx.x, ty = threadIdx.y;
    const float* src = K + (size_t)b*Ss*Dd + h*HDd;
    #pragma unroll
    for (int j=0;j<4;j++){
        int tt = t0 + ty + 8*j;
        tile[ty+8*j][tx] = src[(size_t)tt*Dd + d0 + tx];
    }
    __syncthreads();
    float* dst = KT + (size_t)z*HDd*Ss;
    #pragma unroll
    for (int j=0;j<4;j++){
        int dd = d0 + ty + 8*j;
        dst[(size_t)dd*Ss + t0 + tx] = tile[tx][ty+8*j];
    }
}

// ---------------- masked softmax over a 2048-wide row (one block per row) -------
// Mask faithful to source bug: k <= q gets -1e9 (strictly-future attention);
// last row all -1e9 -> uniform 1/S, which falls out naturally.
__global__ void softmax_kernel(float* __restrict__ sc)
{
    __shared__ float r1[8], r2[8];
    int qrow = blockIdx.x, z = blockIdx.y, t = threadIdx.x;
    float* row = sc + ((size_t)z*Ss + qrow)*Ss;
    float v[8]; float mx = -3.4e38f;
    #pragma unroll
    for (int j=0;j<8;j++){
        int k = t + j*256;
        float s = row[k];
        v[j] = (k <= qrow) ? -1e9f : s*0.125f;   // scale 1/sqrt(64) then mask
        mx = fmaxf(mx, v[j]);
    }
    #pragma unroll
    for (int o=16;o;o>>=1) mx = fmaxf(mx, __shfl_xor_sync(0xffffffffu,mx,o));
    if ((t&31)==0) r1[t>>5]=mx;
    __syncthreads();
    float M = r1[0];
    #pragma unroll
    for (int i=1;i<8;i++) M = fmaxf(M, r1[i]);
    float sum = 0.f;
    #pragma unroll
    for (int j=0;j<8;j++){ v[j] = __expf(v[j]-M); sum += v[j]; }
    #pragma unroll
    for (int o=16;o;o>>=1) sum += __shfl_xor_sync(0xffffffffu,sum,o);
    if ((t&31)==0) r2[t>>5]=sum;
    __syncthreads();
    float T=0.f;
    #pragma unroll
    for (int i=0;i<8;i++) T += r2[i];
    float inv = 1.0f / T;
    #pragma unroll
    for (int j=0;j<8;j++) row[t + j*256] = v[j]*inv;
}

// ---------------- tf32 tensor-core GEMM ----------------------------------------
// C[M,N] = A[M,K] @ B[K,N]  (+bias per column) (gelu) (+residual), optional
// (b,h) batched addressing: off = (z/16)*sXb + (z%16)*sXh.
// All M,N,K are exact multiples of the tile sizes used here.
template<int BM,int BN,int BK,int WM,int WN,bool DO_GELU>
__global__ __launch_bounds__(256,2)
void gemm_tf32(const float* __restrict__ A, int lda, long long sAb, long long sAh,
               const float* __restrict__ Bm, int ldb, long long sBb, long long sBh,
               float* __restrict__ C, int ldc, long long sCb, long long sCh,
               int M, int N, int K,
               const float* __restrict__ bias,
               const float* __restrict__ Rm, int ldr)
{
    static_assert(BK == 32, "BK must be 32");
    constexpr int WARPS_M = BM/WM, WARPS_N = BN/WN;
    static_assert(WARPS_M*WARPS_N == 8, "8 warps");
    constexpr int MT  = WM/16, NTn = WN/8;
    __shared__ float As[BM][BK+8];   // [m][k], stride 40 -> conflict-free frag loads
    __shared__ float Bs[BK][BN+8];   // [k][n], stride%32==8 -> conflict-free

    int z  = blockIdx.z;
    int zb = z >> 4, zh = z & 15;
    A  += (size_t)zb*sAb + (size_t)zh*sAh;
    Bm += (size_t)zb*sBb + (size_t)zh*sBh;
    C  += (size_t)zb*sCb + (size_t)zh*sCh;

    int m0 = blockIdx.y*BM, n0 = blockIdx.x*BN;
    int tid = threadIdx.x, warp = tid>>5, lane = tid&31;
    int wm = (warp/WARPS_N)*WM, wn = (warp%WARPS_N)*WN;
    int g = lane>>2, tg = lane&3;

    float acc[MT][NTn][4];
    #pragma unroll
    for (int i=0;i<MT;i++)
        #pragma unroll
        for (int j=0;j<NTn;j++)
            #pragma unroll
            for (int r=0;r<4;r++) acc[i][j][r]=0.f;

    constexpr int LA = BM*BK/1024;   // float4 loads per thread for A tile
    constexpr int LB = BK*BN/1024;

    for (int k0=0; k0<K; k0+=BK){
        #pragma unroll
        for (int i=0;i<LA;i++){
            int idx = tid + i*256;
            int r = idx >> 3, c = idx & 7;           // BK/4 == 8
            float4 vv = *(const float4*)(A + (size_t)(m0+r)*lda + (k0 + c*4));
            float4 cv;
            cv.x = __uint_as_float(f2tf(vv.x));
            cv.y = __uint_as_float(f2tf(vv.y));
            cv.z = __uint_as_float(f2tf(vv.z));
            cv.w = __uint_as_float(f2tf(vv.w));
            *(float4*)&As[r][c*4] = cv;
        }
        #pragma unroll
        for (int i=0;i<LB;i++){
            int idx = tid + i*256;
            int r = idx / (BN/4), c = idx % (BN/4);
            float4 vv = *(const float4*)(Bm + (size_t)(k0+r)*ldb + (n0 + c*4));
            float4 cv;
            cv.x = __uint_as_float(f2tf(vv.x));
            cv.y = __uint_as_float(f2tf(vv.y));
            cv.z = __uint_as_float(f2tf(vv.z));
            cv.w = __uint_as_float(f2tf(vv.w));
            *(float4*)&Bs[r][c*4] = cv;
        }
        __syncthreads();
        #pragma unroll
        for (int ks=0; ks<BK/8; ks++){
            int kr = ks*8 + tg;
            unsigned af[MT][4], bf[NTn][2];
            #pragma unroll
            for (int mt=0; mt<MT; mt++){
                int mr = wm + mt*16 + g;
                af[mt][0] = __float_as_uint(As[mr  ][kr  ]);
                af[mt][1] = __float_as_uint(As[mr+8][kr  ]);
                af[mt][2] = __float_as_uint(As[mr  ][kr+4]);
                af[mt][3] = __float_as_uint(As[mr+8][kr+4]);
            }
            #pragma unroll
            for (int nt=0; nt<NTn; nt++){
                int nc = wn + nt*8 + g;
                bf[nt][0] = __float_as_uint(Bs[kr  ][nc]);
                bf[nt][1] = __float_as_uint(Bs[kr+4][nc]);
            }
            #pragma unroll
            for (int mt=0; mt<MT; mt++)
                #pragma unroll
                for (int nt=0; nt<NTn; nt++)
                    asm volatile(
                        "mma.sync.aligned.m16n8k8.row.col.f32.tf32.tf32.f32 "
                        "{%0,%1,%2,%3}, {%4,%5,%6,%7}, {%8,%9}, {%0,%1,%2,%3};"
                        : "+f"(acc[mt][nt][0]), "+f"(acc[mt][nt][1]),
                          "+f"(acc[mt][nt][2]), "+f"(acc[mt][nt][3])
                        : "r"(af[mt][0]), "r"(af[mt][1]), "r"(af[mt][2]), "r"(af[mt][3]),
                          "r"(bf[nt][0]), "r"(bf[nt][1]));
        }
        __syncthreads();
    }
    // epilogue: bias -> gelu -> residual -> store (float2 per pair)
    #pragma unroll
    for (int mt=0; mt<MT; mt++){
        #pragma unroll
        for (int i=0; i<2; i++){
            int row = m0 + wm + mt*16 + g + i*8;
            #pragma unroll
            for (int nt=0; nt<NTn; nt++){
                int col = n0 + wn + nt*8 + tg*2;
                float v0 = acc[mt][nt][i*2+0];
                float v1 = acc[mt][nt][i*2+1];
                if (bias){ v0 += bias[col]; v1 += bias[col+1]; }
                if (DO_GELU){ v0 = geluf(v0); v1 = geluf(v1); }
                if (Rm){
                    float2 rr = *(const float2*)(Rm + (size_t)row*ldr + col);
                    v0 += rr.x; v1 += rr.y;
                }
                *(float2*)(C + (size_t)row*ldc + col) = make_float2(v0, v1);
            }
        }
    }
}

// ---------------- host-side launch helpers --------------------------------------
static void gemm_main(const float*A,int lda,long long sAb,long long sAh,
                      const float*B,int ldb,long long sBb,long long sBh,
                      float*C,int ldc,long long sCb,long long sCh,
                      int M,int N,int K,int batch,
                      const float*bias,const float*R,int ldr,bool gelu)
{
    dim3 gr(N/128, M/128, batch);
    if (gelu)
        gemm_tf32<128,128,32,64,32,true ><<<gr,256>>>(A,lda,sAb,sAh,B,ldb,sBb,sBh,
                                                      C,ldc,sCb,sCh,M,N,K,bias,R,ldr);
    else
        gemm_tf32<128,128,32,64,32,false><<<gr,256>>>(A,lda,sAb,sAh,B,ldb,sBb,sBh,
                                                      C,ldc,sCb,sCh,M,N,K,bias,R,ldr);
}
static void gemm_pv(const float*A,int lda,long long sAb,long long sAh,
                    const float*B,int ldb,long long sBb,long long sBh,
                    float*C,int ldc,long long sCb,long long sCh,
                    int M,int N,int K,int batch)
{
    dim3 gr(N/64, M/128, batch);
    gemm_tf32<128,64,32,32,32,false><<<gr,256>>>(A,lda,sAb,sAh,B,ldb,sBb,sBh,
                                                 C,ldc,sCb,sCh,M,N,K,
                                                 nullptr,nullptr,0);
}

extern "C" void kernel_launch(void* const* d_in, const int* in_sizes, int n_in,
                              void* d_out, int out_size)
{
    (void)in_sizes; (void)n_in; (void)out_size;
    const float* x   = (const float*)d_in[0];
    const float* wq  = (const float*)d_in[1];
    const float* wk  = (const float*)d_in[2];
    const float* wv  = (const float*)d_in[3];
    const float* wo  = (const float*)d_in[4];
    const float* bo  = (const float*)d_in[5];
    const float* l1g = (const float*)d_in[6];
    const float* l1b = (const float*)d_in[7];
    const float* l2g = (const float*)d_in[8];
    const float* l2b = (const float*)d_in[9];
    const float* w1  = (const float*)d_in[10];
    const float* b1  = (const float*)d_in[11];
    const float* w2  = (const float*)d_in[12];
    const float* b2  = (const float*)d_in[13];
    float* out = (float*)d_out;

    void* p;
    float *y,*q,*k,*kt,*v,*o,*h,*a,*tmid,*sc;
    cudaGetSymbolAddress(&p, g_y ); y    = (float*)p;
    cudaGetSymbolAddress(&p, g_q ); q    = (float*)p;
    cudaGetSymbolAddress(&p, g_k ); k    = (float*)p;
    cudaGetSymbolAddress(&p, g_kt); kt   = (float*)p;
    cudaGetSymbolAddress(&p, g_v ); v    = (float*)p;
    cudaGetSymbolAddress(&p, g_o ); o    = (float*)p;
    cudaGetSymbolAddress(&p, g_h ); h    = (float*)p;
    cudaGetSymbolAddress(&p, g_a ); a    = (float*)p;
    cudaGetSymbolAddress(&p, g_t ); tmid = (float*)p;
    cudaGetSymbolAddress(&p, g_sc); sc   = (float*)p;

    const long long SD = (long long)Ss*Dd;     // per-batch stride in token-major bufs
    const long long SS = (long long)Ss*Ss;     // per-head stride in scores
    dim3 tg(Ss/32, HDd/32, Bb*Hh), tb(32,8);

    for (int pass=0; pass<2; pass++){
        const float* lnin = pass ? h   : x;
        const float* gg   = pass ? l2g : l1g;
        const float* bbv  = pass ? l2b : l1b;
        ln_kernel<<<NTOK,256>>>(lnin, gg, bbv, y);
        // QKV projections
        gemm_main(y,Dd,0,0, wq,Dd,0,0, q,Dd,0,0, NTOK,Dd,Dd, 1, nullptr,nullptr,0,false);
        gemm_main(y,Dd,0,0, wk,Dd,0,0, k,Dd,0,0, NTOK,Dd,Dd, 1, nullptr,nullptr,0,false);
        gemm_main(y,Dd,0,0, wv,Dd,0,0, v,Dd,0,0, NTOK,Dd,Dd, 1, nullptr,nullptr,0,false);
        // per-head K transpose -> [z][d][t]
        transpose_k_kernel<<<tg,tb>>>(k, kt);
        // scores[z] = Q_z @ K_z^T   (batched over b,h; NN thanks to transpose)
        gemm_main(q ,Dd, SD, 64,
                  kt,Ss, (long long)Hh*HDd*Ss, (long long)HDd*Ss,
                  sc,Ss, (long long)Hh*SS, SS,
                  Ss,Ss,HDd, Bb*Hh, nullptr,nullptr,0,false);
        softmax_kernel<<<dim3(Ss, Bb*Hh),256>>>(sc);
        // O_z = P_z @ V_z
        gemm_pv(sc,Ss, (long long)Hh*SS, SS,
                v ,Dd, SD, 64,
                o ,Dd, SD, 64,
                Ss,HDd,Ss, Bb*Hh);
        // output projection (+bias, +residual on pass 0)
        if (pass == 0)
            gemm_main(o,Dd,0,0, wo,Dd,0,0, h,Dd,0,0, NTOK,Dd,Dd,1, bo, x, Dd, false);
        else
            gemm_main(o,Dd,0,0, wo,Dd,0,0, a,Dd,0,0, NTOK,Dd,Dd,1, bo, nullptr,0, false);
    }
    // FFN: t = gelu(a@w1 + b1);  out = t@w2 + b2 + h
    gemm_main(a   ,Dd,0,0, w1,Ff,0,0, tmid,Ff,0,0, NTOK,Ff,Dd,1, b1, nullptr,0, true );
    gemm_main(tmid,Ff,0,0, w2,Dd,0,0, out ,Dd,0,0, NTOK,Dd,Ff,1, b2, h, Dd,      false);
}

// round 6
// speedup vs baseline: 1.5246x; 1.5246x over previous
#include <cuda_runtime.h>
#include <math.h>

#define Bb   2
#define Ss   2048
#define Dd   1024
#define Hh   16
#define HDd  64
#define Ff   4096
#define NTOK (Bb*Ss)   // 4096

// ---------------- scratch (device globals) --------------------------------------
__device__ float g_y [NTOK*Dd];                 // LN output
__device__ float g_q [NTOK*Dd];
__device__ float g_k [NTOK*Dd];
__device__ float g_v [NTOK*Dd];
__device__ float g_o [NTOK*Dd];                 // attention output (pre-proj)
__device__ float g_h [NTOK*Dd];                 // residual stream after block 1
__device__ float g_a [NTOK*Dd];                 // attention-2 projection output
__device__ float g_t [NTOK*Ff];                 // FFN intermediate

// ---------------- helpers -------------------------------------------------------
__device__ __forceinline__ unsigned f2tf(float x){
    unsigned u; asm("cvt.rna.tf32.f32 %0, %1;" : "=r"(u) : "f"(x)); return u;
}
__device__ __forceinline__ float geluf(float x){
    return 0.5f * x * (1.0f + erff(x * 0.70710678118654752f));
}
__device__ __forceinline__ void mma8(float* c, const unsigned* a, unsigned b0, unsigned b1){
    asm volatile(
        "mma.sync.aligned.m16n8k8.row.col.f32.tf32.tf32.f32 "
        "{%0,%1,%2,%3}, {%4,%5,%6,%7}, {%8,%9}, {%0,%1,%2,%3};"
        : "+f"(c[0]), "+f"(c[1]), "+f"(c[2]), "+f"(c[3])
        : "r"(a[0]), "r"(a[1]), "r"(a[2]), "r"(a[3]), "r"(b0), "r"(b1));
}

// ---------------- LayerNorm -----------------------------------------------------
__global__ void ln_kernel(const float* __restrict__ x,
                          const float* __restrict__ gam,
                          const float* __restrict__ bet,
                          float* __restrict__ y)
{
    __shared__ float rs[2][8];
    int row = blockIdx.x, t = threadIdx.x;
    float4 v = ((const float4*)(x + (size_t)row*Dd))[t];
    float s = v.x+v.y+v.z+v.w;
    float q = v.x*v.x+v.y*v.y+v.z*v.z+v.w*v.w;
    #pragma unroll
    for (int o=16;o;o>>=1){ s += __shfl_xor_sync(0xffffffffu,s,o);
                            q += __shfl_xor_sync(0xffffffffu,q,o); }
    if ((t&31)==0){ rs[0][t>>5]=s; rs[1][t>>5]=q; }
    __syncthreads();
    float S=0.f,Q=0.f;
    #pragma unroll
    for (int i=0;i<8;i++){ S+=rs[0][i]; Q+=rs[1][i]; }
    float mu = S*(1.0f/Dd);
    float var = Q*(1.0f/Dd) - mu*mu;
    float rstd = rsqrtf(var + 1e-5f);
    float4 g4 = ((const float4*)gam)[t];
    float4 b4 = ((const float4*)bet)[t];
    float4 o4;
    o4.x = (v.x-mu)*rstd*g4.x + b4.x;
    o4.y = (v.y-mu)*rstd*g4.y + b4.y;
    o4.z = (v.z-mu)*rstd*g4.z + b4.z;
    o4.w = (v.w-mu)*rstd*g4.w + b4.w;
    ((float4*)(y + (size_t)row*Dd))[t] = o4;
}

// ---------------- flash attention (tf32 mma, online softmax) --------------------
// One block = one (b,h) head z and one 128-row q-tile. 8 warps, warp w owns
// q-rows [16w,16w+16). Mask faithful to source bug: k <= q -> -1e9 (strictly
// future attention); fully-masked rows degrade to uniform softmax naturally.
// Strides chosen conflict-free: Qs/Ks 68 (=4 mod 32), Vs 72 (=8 mod 32),
// Ps 132 (=4 mod 32).
#define QS_LD 68
#define VS_LD 72
#define PS_LD 132
#define FLASH_SMEM ((128*QS_LD*2 + 128*VS_LD + 128*PS_LD) * 4)

__global__ __launch_bounds__(256,1)
void flash_kernel(const float* __restrict__ Q, const float* __restrict__ K,
                  const float* __restrict__ V, float* __restrict__ O)
{
    extern __shared__ float sm[];
    float* Qs = sm;                    // [128][68]
    float* Ks = Qs + 128*QS_LD;        // [128][68]
    float* Vs = Ks + 128*QS_LD;        // [128][72]
    float* Ps = Vs + 128*VS_LD;        // [128][132]

    int qt = 15 - blockIdx.x;          // heavy (qt=15) blocks first
    int z = blockIdx.y, b = z >> 4, h = z & 15;
    const float* Qp = Q + (size_t)b*Ss*Dd + h*HDd;
    const float* Kp = K + (size_t)b*Ss*Dd + h*HDd;
    const float* Vp = V + (size_t)b*Ss*Dd + h*HDd;
    float*       Op = O + (size_t)b*Ss*Dd + h*HDd;

    int tid = threadIdx.x, warp = tid>>5, lane = tid&31;
    int g = lane>>2, tg = lane&3;
    int q0 = qt*128;

    // load Q tile (tf32) once
    #pragma unroll
    for (int i=0;i<8;i++){
        int idx = tid + i*256;
        int r = idx>>4, c4 = idx&15;
        float4 v4 = *(const float4*)(Qp + (size_t)(q0+r)*Dd + c4*4);
        float4 cv;
        cv.x=__uint_as_float(f2tf(v4.x)); cv.y=__uint_as_float(f2tf(v4.y));
        cv.z=__uint_as_float(f2tf(v4.z)); cv.w=__uint_as_float(f2tf(v4.w));
        *(float4*)&Qs[r*QS_LD + c4*4] = cv;
    }
    __syncthreads();

    // Q fragments to registers (held for whole kernel)
    unsigned qf[8][4];
    int pr0 = warp*16 + g;
    #pragma unroll
    for (int kc=0;kc<8;kc++){
        qf[kc][0] = __float_as_uint(Qs[ pr0   *QS_LD + kc*8+tg  ]);
        qf[kc][1] = __float_as_uint(Qs[(pr0+8)*QS_LD + kc*8+tg  ]);
        qf[kc][2] = __float_as_uint(Qs[ pr0   *QS_LD + kc*8+tg+4]);
        qf[kc][3] = __float_as_uint(Qs[(pr0+8)*QS_LD + kc*8+tg+4]);
    }

    float oa[8][4];
    #pragma unroll
    for (int i=0;i<8;i++){ oa[i][0]=0.f;oa[i][1]=0.f;oa[i][2]=0.f;oa[i][3]=0.f; }
    float m0=-1e30f, m1=-1e30f, l0=0.f, l1=0.f;
    int grow0 = q0 + pr0, grow1 = grow0 + 8;

    // Tiles kt<qt are fully masked for every row in this q-tile; skipping them
    // is exact because each such row has >=1 valid key in tiles kt>=qt, whose
    // online-max sends the masked exp's to 0. Exception: qt==15 contains row
    // 2047 (no valid key -> uniform softmax over ALL keys), so include all tiles.
    int kt0 = (qt==15) ? 0 : qt;
    for (int kt=kt0; kt<16; kt++){
        __syncthreads();   // previous PV done before overwriting Ks/Vs
        #pragma unroll
        for (int i=0;i<8;i++){
            int idx = tid + i*256;
            int r = idx>>4, c4 = idx&15;
            float4 kv = *(const float4*)(Kp + (size_t)(kt*128+r)*Dd + c4*4);
            float4 ck;
            ck.x=__uint_as_float(f2tf(kv.x)); ck.y=__uint_as_float(f2tf(kv.y));
            ck.z=__uint_as_float(f2tf(kv.z)); ck.w=__uint_as_float(f2tf(kv.w));
            *(float4*)&Ks[r*QS_LD + c4*4] = ck;
            float4 vv = *(const float4*)(Vp + (size_t)(kt*128+r)*Dd + c4*4);
            float4 cv;
            cv.x=__uint_as_float(f2tf(vv.x)); cv.y=__uint_as_float(f2tf(vv.y));
            cv.z=__uint_as_float(f2tf(vv.z)); cv.w=__uint_as_float(f2tf(vv.w));
            *(float4*)&Vs[r*VS_LD + c4*4] = cv;
        }
        __syncthreads();

        // S = Q @ K^T for this warp's 16 rows x 128 keys
        float sc[16][4];
        #pragma unroll
        for (int nt=0;nt<16;nt++){ sc[nt][0]=0.f;sc[nt][1]=0.f;sc[nt][2]=0.f;sc[nt][3]=0.f; }
        #pragma unroll
        for (int kc=0;kc<8;kc++){
            #pragma unroll
            for (int nt=0;nt<16;nt++){
                unsigned b0 = __float_as_uint(Ks[(nt*8+g)*QS_LD + kc*8+tg  ]);
                unsigned b1 = __float_as_uint(Ks[(nt*8+g)*QS_LD + kc*8+tg+4]);
                mma8(sc[nt], qf[kc], b0, b1);
            }
        }

        // scale + mask + online softmax
        float tm0=-1e30f, tm1=-1e30f;
        #pragma unroll
        for (int nt=0;nt<16;nt++){
            #pragma unroll
            for (int j=0;j<4;j++){
                int gcol = kt*128 + nt*8 + tg*2 + (j&1);
                int grow = (j<2) ? grow0 : grow1;
                float s = (gcol<=grow) ? -1e9f : sc[nt][j]*0.125f;
                sc[nt][j] = s;
                if (j<2) tm0 = fmaxf(tm0,s); else tm1 = fmaxf(tm1,s);
            }
        }
        tm0 = fmaxf(tm0, __shfl_xor_sync(0xffffffffu,tm0,1));
        tm0 = fmaxf(tm0, __shfl_xor_sync(0xffffffffu,tm0,2));
        tm1 = fmaxf(tm1, __shfl_xor_sync(0xffffffffu,tm1,1));
        tm1 = fmaxf(tm1, __shfl_xor_sync(0xffffffffu,tm1,2));
        float mn0 = fmaxf(m0,tm0), mn1 = fmaxf(m1,tm1);
        float sf0 = __expf(m0-mn0), sf1 = __expf(m1-mn1);
        float rs0=0.f, rs1=0.f;
        #pragma unroll
        for (int nt=0;nt<16;nt++){
            sc[nt][0] = __expf(sc[nt][0]-mn0); rs0 += sc[nt][0];
            sc[nt][1] = __expf(sc[nt][1]-mn0); rs0 += sc[nt][1];
            sc[nt][2] = __expf(sc[nt][2]-mn1); rs1 += sc[nt][2];
            sc[nt][3] = __expf(sc[nt][3]-mn1); rs1 += sc[nt][3];
        }
        rs0 += __shfl_xor_sync(0xffffffffu,rs0,1);
        rs0 += __shfl_xor_sync(0xffffffffu,rs0,2);
        rs1 += __shfl_xor_sync(0xffffffffu,rs1,1);
        rs1 += __shfl_xor_sync(0xffffffffu,rs1,2);
        l0 = l0*sf0 + rs0;  l1 = l1*sf1 + rs1;
        m0 = mn0;  m1 = mn1;
        #pragma unroll
        for (int i=0;i<8;i++){
            oa[i][0]*=sf0; oa[i][1]*=sf0; oa[i][2]*=sf1; oa[i][3]*=sf1;
        }

        // stage P to smem (warp-local rows), then PV
        #pragma unroll
        for (int nt=0;nt<16;nt++){
            float2 pa, pb;
            pa.x = __uint_as_float(f2tf(sc[nt][0]));
            pa.y = __uint_as_float(f2tf(sc[nt][1]));
            pb.x = __uint_as_float(f2tf(sc[nt][2]));
            pb.y = __uint_as_float(f2tf(sc[nt][3]));
            *(float2*)&Ps[ pr0   *PS_LD + nt*8 + tg*2] = pa;
            *(float2*)&Ps[(pr0+8)*PS_LD + nt*8 + tg*2] = pb;
        }
        __syncwarp();
        #pragma unroll
        for (int kc2=0;kc2<16;kc2++){
            unsigned pf[4];
            pf[0] = __float_as_uint(Ps[ pr0   *PS_LD + kc2*8+tg  ]);
            pf[1] = __float_as_uint(Ps[(pr0+8)*PS_LD + kc2*8+tg  ]);
            pf[2] = __float_as_uint(Ps[ pr0   *PS_LD + kc2*8+tg+4]);
            pf[3] = __float_as_uint(Ps[(pr0+8)*PS_LD + kc2*8+tg+4]);
            #pragma unroll
            for (int nt2=0;nt2<8;nt2++){
                unsigned b0 = __float_as_uint(Vs[(kc2*8+tg  )*VS_LD + nt2*8+g]);
                unsigned b1 = __float_as_uint(Vs[(kc2*8+tg+4)*VS_LD + nt2*8+g]);
                mma8(oa[nt2], pf, b0, b1);
            }
        }
    }

    float inv0 = 1.f/l0, inv1 = 1.f/l1;
    #pragma unroll
    for (int nt2=0;nt2<8;nt2++){
        float2 w0 = make_float2(oa[nt2][0]*inv0, oa[nt2][1]*inv0);
        float2 w1 = make_float2(oa[nt2][2]*inv1, oa[nt2][3]*inv1);
        *(float2*)(Op + (size_t)grow0*Dd + nt2*8 + tg*2) = w0;
        *(float2*)(Op + (size_t)grow1*Dd + nt2*8 + tg*2) = w1;
    }
}

// ---------------- tf32 tensor-core GEMM ----------------------------------------
// C[M,N] = A[M,K] @ B[K,N]  (+bias) (gelu) (+residual).
// As padded +4 (stride 36 = 4 mod 32): A-frag banks (4g+tg) all-distinct.
// Bs padded +8 (stride 136 = 8 mod 32): B-frag banks (8tg+g) all-distinct.
template<int BM,int BN,int BK,int WM,int WN,bool DO_GELU>
__global__ __launch_bounds__(256,2)
void gemm_tf32(const float* __restrict__ A, int lda,
               const float* __restrict__ Bm, int ldb,
               float* __restrict__ C, int ldc,
               int M, int N, int K,
               const float* __restrict__ bias,
               const float* __restrict__ Rm, int ldr)
{
    static_assert(BK == 32, "BK must be 32");
    constexpr int WARPS_M = BM/WM, WARPS_N = BN/WN;
    static_assert(WARPS_M*WARPS_N == 8, "8 warps");
    constexpr int MT  = WM/16, NTn = WN/8;
    __shared__ float As[BM][BK+4];
    __shared__ float Bs[BK][BN+8];

    int m0 = blockIdx.y*BM, n0 = blockIdx.x*BN;
    int tid = threadIdx.x, warp = tid>>5, lane = tid&31;
    int wm = (warp/WARPS_N)*WM, wn = (warp%WARPS_N)*WN;
    int g = lane>>2, tg = lane&3;

    float acc[MT][NTn][4];
    #pragma unroll
    for (int i=0;i<MT;i++)
        #pragma unroll
        for (int j=0;j<NTn;j++)
            #pragma unroll
            for (int r=0;r<4;r++) acc[i][j][r]=0.f;

    constexpr int LA = BM*BK/1024;
    constexpr int LB = BK*BN/1024;

    for (int k0=0; k0<K; k0+=BK){
        #pragma unroll
        for (int i=0;i<LA;i++){
            int idx = tid + i*256;
            int r = idx >> 3, c = idx & 7;
            float4 vv = *(const float4*)(A + (size_t)(m0+r)*lda + (k0 + c*4));
            float4 cv;
            cv.x = __uint_as_float(f2tf(vv.x));
            cv.y = __uint_as_float(f2tf(vv.y));
            cv.z = __uint_as_float(f2tf(vv.z));
            cv.w = __uint_as_float(f2tf(vv.w));
            *(float4*)&As[r][c*4] = cv;
        }
        #pragma unroll
        for (int i=0;i<LB;i++){
            int idx = tid + i*256;
            int r = idx / (BN/4), c = idx % (BN/4);
            float4 vv = *(const float4*)(Bm + (size_t)(k0+r)*ldb + (n0 + c*4));
            float4 cv;
            cv.x = __uint_as_float(f2tf(vv.x));
            cv.y = __uint_as_float(f2tf(vv.y));
            cv.z = __uint_as_float(f2tf(vv.z));
            cv.w = __uint_as_float(f2tf(vv.w));
            *(float4*)&Bs[r][c*4] = cv;
        }
        __syncthreads();
        #pragma unroll
        for (int ks=0; ks<BK/8; ks++){
            int kr = ks*8 + tg;
            unsigned af[MT][4], bf[NTn][2];
            #pragma unroll
            for (int mt=0; mt<MT; mt++){
                int mr = wm + mt*16 + g;
                af[mt][0] = __float_as_uint(As[mr  ][kr  ]);
                af[mt][1] = __float_as_uint(As[mr+8][kr  ]);
                af[mt][2] = __float_as_uint(As[mr  ][kr+4]);
                af[mt][3] = __float_as_uint(As[mr+8][kr+4]);
            }
            #pragma unroll
            for (int nt=0; nt<NTn; nt++){
                int nc = wn + nt*8 + g;
                bf[nt][0] = __float_as_uint(Bs[kr  ][nc]);
                bf[nt][1] = __float_as_uint(Bs[kr+4][nc]);
            }
            #pragma unroll
            for (int mt=0; mt<MT; mt++)
                #pragma unroll
                for (int nt=0; nt<NTn; nt++)
                    mma8(acc[mt][nt], af[mt], bf[nt][0], bf[nt][1]);
        }
        __syncthreads();
    }
    #pragma unroll
    for (int mt=0; mt<MT; mt++){
        #pragma unroll
        for (int i=0; i<2; i++){
            int row = m0 + wm + mt*16 + g + i*8;
            #pragma unroll
            for (int nt=0; nt<NTn; nt++){
                int col = n0 + wn + nt*8 + tg*2;
                float v0 = acc[mt][nt][i*2+0];
                float v1 = acc[mt][nt][i*2+1];
                if (bias){ v0 += bias[col]; v1 += bias[col+1]; }
                if (DO_GELU){ v0 = geluf(v0); v1 = geluf(v1); }
                if (Rm){
                    float2 rr = *(const float2*)(Rm + (size_t)row*ldr + col);
                    v0 += rr.x; v1 += rr.y;
                }
                *(float2*)(C + (size_t)row*ldc + col) = make_float2(v0, v1);
            }
        }
    }
}

// ---------------- host-side launch helper ---------------------------------------
static void gemm_main(const float*A,int lda, const float*B,int ldb,
                      float*C,int ldc, int M,int N,int K,
                      const float*bias,const float*R,int ldr,bool gelu)
{
    dim3 gr(N/128, M/128, 1);
    if (gelu)
        gemm_tf32<128,128,32,64,32,true ><<<gr,256>>>(A,lda,B,ldb,C,ldc,M,N,K,bias,R,ldr);
    else
        gemm_tf32<128,128,32,64,32,false><<<gr,256>>>(A,lda,B,ldb,C,ldc,M,N,K,bias,R,ldr);
}

extern "C" void kernel_launch(void* const* d_in, const int* in_sizes, int n_in,
                              void* d_out, int out_size)
{
    (void)in_sizes; (void)n_in; (void)out_size;
    const float* x   = (const float*)d_in[0];
    const float* wq  = (const float*)d_in[1];
    const float* wk  = (const float*)d_in[2];
    const float* wv  = (const float*)d_in[3];
    const float* wo  = (const float*)d_in[4];
    const float* bo  = (const float*)d_in[5];
    const float* l1g = (const float*)d_in[6];
    const float* l1b = (const float*)d_in[7];
    const float* l2g = (const float*)d_in[8];
    const float* l2b = (const float*)d_in[9];
    const float* w1  = (const float*)d_in[10];
    const float* b1  = (const float*)d_in[11];
    const float* w2  = (const float*)d_in[12];
    const float* b2  = (const float*)d_in[13];
    float* out = (float*)d_out;

    void* p;
    float *y,*q,*k,*v,*o,*h,*a,*tmid;
    cudaGetSymbolAddress(&p, g_y); y    = (float*)p;
    cudaGetSymbolAddress(&p, g_q); q    = (float*)p;
    cudaGetSymbolAddress(&p, g_k); k    = (float*)p;
    cudaGetSymbolAddress(&p, g_v); v    = (float*)p;
    cudaGetSymbolAddress(&p, g_o); o    = (float*)p;
    cudaGetSymbolAddress(&p, g_h); h    = (float*)p;
    cudaGetSymbolAddress(&p, g_a); a    = (float*)p;
    cudaGetSymbolAddress(&p, g_t); tmid = (float*)p;

    cudaFuncSetAttribute((const void*)flash_kernel,
                         cudaFuncAttributeMaxDynamicSharedMemorySize, FLASH_SMEM);

    for (int pass=0; pass<2; pass++){
        const float* lnin = pass ? h   : x;
        const float* gg   = pass ? l2g : l1g;
        const float* bbv  = pass ? l2b : l1b;
        ln_kernel<<<NTOK,256>>>(lnin, gg, bbv, y);
        gemm_main(y,Dd, wq,Dd, q,Dd, NTOK,Dd,Dd, nullptr,nullptr,0,false);
        gemm_main(y,Dd, wk,Dd, k,Dd, NTOK,Dd,Dd, nullptr,nullptr,0,false);
        gemm_main(y,Dd, wv,Dd, v,Dd, NTOK,Dd,Dd, nullptr,nullptr,0,false);
        flash_kernel<<<dim3(16,32),256,FLASH_SMEM>>>(q, k, v, o);
        if (pass == 0)
            gemm_main(o,Dd, wo,Dd, h,Dd, NTOK,Dd,Dd, bo, x, Dd, false);
        else
            gemm_main(o,Dd, wo,Dd, a,Dd, NTOK,Dd,Dd, bo, nullptr,0, false);
    }
    // FFN: t = gelu(a@w1 + b1);  out = t@w2 + b2 + h
    gemm_main(a   ,Dd, w1,Ff, tmid,Ff, NTOK,Ff,Dd, b1, nullptr,0, true );
    gemm_main(tmid,Ff, w2,Dd, out ,Dd, NTOK,Dd,Ff, b2, h, Dd,      false);
}

// round 7
// speedup vs baseline: 1.7869x; 1.1720x over previous
#include <cuda_runtime.h>
#include <math.h>

#define Bb   2
#define Ss   2048
#define Dd   1024
#define Hh   16
#define HDd  64
#define Ff   4096
#define NTOK (Bb*Ss)   // 4096

// ---------------- scratch (device globals) --------------------------------------
__device__ float g_y [NTOK*Dd];                 // LN output (tf32-rounded)
__device__ float g_q [NTOK*Dd];
__device__ float g_k [NTOK*Dd];
__device__ float g_v [NTOK*Dd];
__device__ float g_o [NTOK*Dd];                 // attention out (tf32-rounded)
__device__ float g_h [NTOK*Dd];                 // residual stream (exact f32)
__device__ float g_a [NTOK*Dd];                 // attn-2 proj out (tf32-rounded)
__device__ float g_t [NTOK*Ff];                 // FFN mid (tf32-rounded)
// tf32-rounded weight copies
__device__ float g_wq[Dd*Dd], g_wk[Dd*Dd], g_wv[Dd*Dd], g_wo[Dd*Dd];
__device__ float g_w1[Dd*Ff], g_w2[Ff*Dd];

// ---------------- helpers -------------------------------------------------------
__device__ __forceinline__ unsigned f2tf(float x){
    unsigned u; asm("cvt.rna.tf32.f32 %0, %1;" : "=r"(u) : "f"(x)); return u;
}
__device__ __forceinline__ float rndtf(float x){ return __uint_as_float(f2tf(x)); }
__device__ __forceinline__ float geluf(float x){
    return 0.5f * x * (1.0f + erff(x * 0.70710678118654752f));
}
__device__ __forceinline__ void mma8(float* c, const unsigned* a, unsigned b0, unsigned b1){
    asm volatile(
        "mma.sync.aligned.m16n8k8.row.col.f32.tf32.tf32.f32 "
        "{%0,%1,%2,%3}, {%4,%5,%6,%7}, {%8,%9}, {%0,%1,%2,%3};"
        : "+f"(c[0]), "+f"(c[1]), "+f"(c[2]), "+f"(c[3])
        : "r"(a[0]), "r"(a[1]), "r"(a[2]), "r"(a[3]), "r"(b0), "r"(b1));
}
__device__ __forceinline__ void cpa16(float* dst, const float* src){
    unsigned d = (unsigned)__cvta_generic_to_shared(dst);
    asm volatile("cp.async.cg.shared.global [%0], [%1], 16;" :: "r"(d), "l"(src));
}
__device__ __forceinline__ void cp_commit(){ asm volatile("cp.async.commit_group;"); }
template<int N> __device__ __forceinline__ void cp_wait(){
    asm volatile("cp.async.wait_group %0;" :: "n"(N));
}

// ---------------- weight/tensor tf32 rounding pass ------------------------------
__global__ void round_kernel(const float* __restrict__ in, float* __restrict__ out, int n4)
{
    int i = blockIdx.x*blockDim.x + threadIdx.x;
    if (i < n4){
        float4 v = ((const float4*)in)[i];
        v.x = rndtf(v.x); v.y = rndtf(v.y); v.z = rndtf(v.z); v.w = rndtf(v.w);
        ((float4*)out)[i] = v;
    }
}

// ---------------- LayerNorm (output pre-rounded to tf32) ------------------------
__global__ void ln_kernel(const float* __restrict__ x,
                          const float* __restrict__ gam,
                          const float* __restrict__ bet,
                          float* __restrict__ y)
{
    __shared__ float rs[2][8];
    int row = blockIdx.x, t = threadIdx.x;
    float4 v = ((const float4*)(x + (size_t)row*Dd))[t];
    float s = v.x+v.y+v.z+v.w;
    float q = v.x*v.x+v.y*v.y+v.z*v.z+v.w*v.w;
    #pragma unroll
    for (int o=16;o;o>>=1){ s += __shfl_xor_sync(0xffffffffu,s,o);
                            q += __shfl_xor_sync(0xffffffffu,q,o); }
    if ((t&31)==0){ rs[0][t>>5]=s; rs[1][t>>5]=q; }
    __syncthreads();
    float S=0.f,Q=0.f;
    #pragma unroll
    for (int i=0;i<8;i++){ S+=rs[0][i]; Q+=rs[1][i]; }
    float mu = S*(1.0f/Dd);
    float var = Q*(1.0f/Dd) - mu*mu;
    float rstd = rsqrtf(var + 1e-5f);
    float4 g4 = ((const float4*)gam)[t];
    float4 b4 = ((const float4*)bet)[t];
    float4 o4;
    o4.x = rndtf((v.x-mu)*rstd*g4.x + b4.x);
    o4.y = rndtf((v.y-mu)*rstd*g4.y + b4.y);
    o4.z = rndtf((v.z-mu)*rstd*g4.z + b4.z);
    o4.w = rndtf((v.w-mu)*rstd*g4.w + b4.w);
    ((float4*)(y + (size_t)row*Dd))[t] = o4;
}

// ---------------- flash attention (tf32 mma, online softmax) --------------------
#define QS_LD 68
#define VS_LD 72
#define PS_LD 132
#define FLASH_SMEM ((128*QS_LD*2 + 128*VS_LD + 128*PS_LD) * 4)

__global__ __launch_bounds__(256,1)
void flash_kernel(const float* __restrict__ Q, const float* __restrict__ K,
                  const float* __restrict__ V, float* __restrict__ O)
{
    extern __shared__ float sm[];
    float* Qs = sm;
    float* Ks = Qs + 128*QS_LD;
    float* Vs = Ks + 128*QS_LD;
    float* Ps = Vs + 128*VS_LD;

    int qt = 15 - blockIdx.x;
    int z = blockIdx.y, b = z >> 4, h = z & 15;
    const float* Qp = Q + (size_t)b*Ss*Dd + h*HDd;
    const float* Kp = K + (size_t)b*Ss*Dd + h*HDd;
    const float* Vp = V + (size_t)b*Ss*Dd + h*HDd;
    float*       Op = O + (size_t)b*Ss*Dd + h*HDd;

    int tid = threadIdx.x, warp = tid>>5, lane = tid&31;
    int g = lane>>2, tg = lane&3;
    int q0 = qt*128;

    #pragma unroll
    for (int i=0;i<8;i++){
        int idx = tid + i*256;
        int r = idx>>4, c4 = idx&15;
        float4 v4 = *(const float4*)(Qp + (size_t)(q0+r)*Dd + c4*4);
        float4 cv;
        cv.x=rndtf(v4.x); cv.y=rndtf(v4.y); cv.z=rndtf(v4.z); cv.w=rndtf(v4.w);
        *(float4*)&Qs[r*QS_LD + c4*4] = cv;
    }
    __syncthreads();

    unsigned qf[8][4];
    int pr0 = warp*16 + g;
    #pragma unroll
    for (int kc=0;kc<8;kc++){
        qf[kc][0] = __float_as_uint(Qs[ pr0   *QS_LD + kc*8+tg  ]);
        qf[kc][1] = __float_as_uint(Qs[(pr0+8)*QS_LD + kc*8+tg  ]);
        qf[kc][2] = __float_as_uint(Qs[ pr0   *QS_LD + kc*8+tg+4]);
        qf[kc][3] = __float_as_uint(Qs[(pr0+8)*QS_LD + kc*8+tg+4]);
    }

    float oa[8][4];
    #pragma unroll
    for (int i=0;i<8;i++){ oa[i][0]=0.f;oa[i][1]=0.f;oa[i][2]=0.f;oa[i][3]=0.f; }
    float m0=-1e30f, m1=-1e30f, l0=0.f, l1=0.f;
    int grow0 = q0 + pr0, grow1 = grow0 + 8;

    int kt0 = (qt==15) ? 0 : qt;
    for (int kt=kt0; kt<16; kt++){
        __syncthreads();
        #pragma unroll
        for (int i=0;i<8;i++){
            int idx = tid + i*256;
            int r = idx>>4, c4 = idx&15;
            float4 kv = *(const float4*)(Kp + (size_t)(kt*128+r)*Dd + c4*4);
            float4 ck;
            ck.x=rndtf(kv.x); ck.y=rndtf(kv.y); ck.z=rndtf(kv.z); ck.w=rndtf(kv.w);
            *(float4*)&Ks[r*QS_LD + c4*4] = ck;
            float4 vv = *(const float4*)(Vp + (size_t)(kt*128+r)*Dd + c4*4);
            float4 cv;
            cv.x=rndtf(vv.x); cv.y=rndtf(vv.y); cv.z=rndtf(vv.z); cv.w=rndtf(vv.w);
            *(float4*)&Vs[r*VS_LD + c4*4] = cv;
        }
        __syncthreads();

        float sc[16][4];
        #pragma unroll
        for (int nt=0;nt<16;nt++){ sc[nt][0]=0.f;sc[nt][1]=0.f;sc[nt][2]=0.f;sc[nt][3]=0.f; }
        #pragma unroll
        for (int kc=0;kc<8;kc++){
            #pragma unroll
            for (int nt=0;nt<16;nt++){
                unsigned b0 = __float_as_uint(Ks[(nt*8+g)*QS_LD + kc*8+tg  ]);
                unsigned b1 = __float_as_uint(Ks[(nt*8+g)*QS_LD + kc*8+tg+4]);
                mma8(sc[nt], qf[kc], b0, b1);
            }
        }

        float tm0=-1e30f, tm1=-1e30f;
        #pragma unroll
        for (int nt=0;nt<16;nt++){
            #pragma unroll
            for (int j=0;j<4;j++){
                int gcol = kt*128 + nt*8 + tg*2 + (j&1);
                int grow = (j<2) ? grow0 : grow1;
                float s = (gcol<=grow) ? -1e9f : sc[nt][j]*0.125f;
                sc[nt][j] = s;
                if (j<2) tm0 = fmaxf(tm0,s); else tm1 = fmaxf(tm1,s);
            }
        }
        tm0 = fmaxf(tm0, __shfl_xor_sync(0xffffffffu,tm0,1));
        tm0 = fmaxf(tm0, __shfl_xor_sync(0xffffffffu,tm0,2));
        tm1 = fmaxf(tm1, __shfl_xor_sync(0xffffffffu,tm1,1));
        tm1 = fmaxf(tm1, __shfl_xor_sync(0xffffffffu,tm1,2));
        float mn0 = fmaxf(m0,tm0), mn1 = fmaxf(m1,tm1);
        float sf0 = __expf(m0-mn0), sf1 = __expf(m1-mn1);
        float rs0=0.f, rs1=0.f;
        #pragma unroll
        for (int nt=0;nt<16;nt++){
            sc[nt][0] = __expf(sc[nt][0]-mn0); rs0 += sc[nt][0];
            sc[nt][1] = __expf(sc[nt][1]-mn0); rs0 += sc[nt][1];
            sc[nt][2] = __expf(sc[nt][2]-mn1); rs1 += sc[nt][2];
            sc[nt][3] = __expf(sc[nt][3]-mn1); rs1 += sc[nt][3];
        }
        rs0 += __shfl_xor_sync(0xffffffffu,rs0,1);
        rs0 += __shfl_xor_sync(0xffffffffu,rs0,2);
        rs1 += __shfl_xor_sync(0xffffffffu,rs1,1);
        rs1 += __shfl_xor_sync(0xffffffffu,rs1,2);
        l0 = l0*sf0 + rs0;  l1 = l1*sf1 + rs1;
        m0 = mn0;  m1 = mn1;
        #pragma unroll
        for (int i=0;i<8;i++){
            oa[i][0]*=sf0; oa[i][1]*=sf0; oa[i][2]*=sf1; oa[i][3]*=sf1;
        }

        #pragma unroll
        for (int nt=0;nt<16;nt++){
            float2 pa, pb;
            pa.x = rndtf(sc[nt][0]); pa.y = rndtf(sc[nt][1]);
            pb.x = rndtf(sc[nt][2]); pb.y = rndtf(sc[nt][3]);
            *(float2*)&Ps[ pr0   *PS_LD + nt*8 + tg*2] = pa;
            *(float2*)&Ps[(pr0+8)*PS_LD + nt*8 + tg*2] = pb;
        }
        __syncwarp();
        #pragma unroll
        for (int kc2=0;kc2<16;kc2++){
            unsigned pf[4];
            pf[0] = __float_as_uint(Ps[ pr0   *PS_LD + kc2*8+tg  ]);
            pf[1] = __float_as_uint(Ps[(pr0+8)*PS_LD + kc2*8+tg  ]);
            pf[2] = __float_as_uint(Ps[ pr0   *PS_LD + kc2*8+tg+4]);
            pf[3] = __float_as_uint(Ps[(pr0+8)*PS_LD + kc2*8+tg+4]);
            #pragma unroll
            for (int nt2=0;nt2<8;nt2++){
                unsigned b0 = __float_as_uint(Vs[(kc2*8+tg  )*VS_LD + nt2*8+g]);
                unsigned b1 = __float_as_uint(Vs[(kc2*8+tg+4)*VS_LD + nt2*8+g]);
                mma8(oa[nt2], pf, b0, b1);
            }
        }
    }

    // output rounded to tf32 (it feeds the O-projection GEMM as A)
    float inv0 = 1.f/l0, inv1 = 1.f/l1;
    #pragma unroll
    for (int nt2=0;nt2<8;nt2++){
        float2 w0 = make_float2(rndtf(oa[nt2][0]*inv0), rndtf(oa[nt2][1]*inv0));
        float2 w1 = make_float2(rndtf(oa[nt2][2]*inv1), rndtf(oa[nt2][3]*inv1));
        *(float2*)(Op + (size_t)grow0*Dd + nt2*8 + tg*2) = w0;
        *(float2*)(Op + (size_t)grow1*Dd + nt2*8 + tg*2) = w1;
    }
}

// ---------------- pipelined tf32 GEMM (cp.async double-buffered) ----------------
// Operands must already be tf32-rounded (producers round at store time).
// As stride 36 (=4 mod 32): A-frag banks (4g+tg) all distinct.
// Bs stride 136 (=8 mod 32): B-frag banks (8tg+g) all distinct.
#define AS_LD 36
#define BS_LD 136
#define A_STG (128*AS_LD)         // floats per A stage
#define B_STG (32*BS_LD)
#define GEMM_SMEM ((2*A_STG + 2*B_STG)*4)   // 71680 B

template<bool DO_GELU, bool ROUND_OUT>
__global__ __launch_bounds__(256,2)
void gemm_tf32(const float* __restrict__ A, int lda,
               const float* __restrict__ Bm, int ldb,
               float* __restrict__ C, int ldc,
               int M, int N, int K,
               const float* __restrict__ bias,
               const float* __restrict__ Rm, int ldr)
{
    constexpr int BM=128, BN=128, BK=32, WM=64, WN=32;
    constexpr int WARPS_N = BN/WN;
    constexpr int MT = WM/16, NTn = WN/8;
    extern __shared__ float dsm[];

    int m0 = blockIdx.y*BM, n0 = blockIdx.x*BN;
    int tid = threadIdx.x, warp = tid>>5, lane = tid&31;
    int wm = (warp/WARPS_N)*WM, wn = (warp%WARPS_N)*WN;
    int g = lane>>2, tg = lane&3;

    // per-thread copy coordinates (4 chunks each of A and B per stage)
    int ar = tid>>3,  ac = (tid&7)*4;        // A: rows tid/8 + 32*i, col chunk
    int br = tid>>5,  bc = (tid&31)*4;       // B: rows tid/32 + 8*i

    const float* Ab = A  + (size_t)(m0+ar)*lda + ac;
    const float* Bb2= Bm + (size_t)br*ldb + n0 + bc;

    float acc[MT][NTn][4];
    #pragma unroll
    for (int i=0;i<MT;i++)
        #pragma unroll
        for (int j=0;j<NTn;j++)
            #pragma unroll
            for (int r=0;r<4;r++) acc[i][j][r]=0.f;

    auto issue = [&](int k0, int s){
        float* As = dsm + s*A_STG;
        float* Bs = dsm + 2*A_STG + s*B_STG;
        #pragma unroll
        for (int i=0;i<4;i++)
            cpa16(&As[(ar+32*i)*AS_LD + ac], Ab + (size_t)(32*i)*lda + k0);
        #pragma unroll
        for (int i=0;i<4;i++)
            cpa16(&Bs[(br+8*i)*BS_LD + bc], Bb2 + (size_t)(k0+8*i)*ldb);
        cp_commit();
    };

    int nk = K/BK;
    issue(0, 0);
    for (int it=0; it<nk; it++){
        int s = it&1;
        if (it+1 < nk) issue((it+1)*BK, s^1);
        if (it+1 < nk) cp_wait<1>(); else cp_wait<0>();
        __syncthreads();

        float* As = dsm + s*A_STG;
        float* Bs = dsm + 2*A_STG + s*B_STG;
        #pragma unroll
        for (int ks=0; ks<BK/8; ks++){
            int kr = ks*8 + tg;
            unsigned af[MT][4], bf[NTn][2];
            #pragma unroll
            for (int mt=0; mt<MT; mt++){
                int mr = wm + mt*16 + g;
                af[mt][0] = __float_as_uint(As[ mr   *AS_LD + kr  ]);
                af[mt][1] = __float_as_uint(As[(mr+8)*AS_LD + kr  ]);
                af[mt][2] = __float_as_uint(As[ mr   *AS_LD + kr+4]);
                af[mt][3] = __float_as_uint(As[(mr+8)*AS_LD + kr+4]);
            }
            #pragma unroll
            for (int nt=0; nt<NTn; nt++){
                int nc = wn + nt*8 + g;
                bf[nt][0] = __float_as_uint(Bs[ kr   *BS_LD + nc]);
                bf[nt][1] = __float_as_uint(Bs[(kr+4)*BS_LD + nc]);
            }
            #pragma unroll
            for (int mt=0; mt<MT; mt++)
                #pragma unroll
                for (int nt=0; nt<NTn; nt++)
                    mma8(acc[mt][nt], af[mt], bf[nt][0], bf[nt][1]);
        }
        __syncthreads();
    }

    #pragma unroll
    for (int mt=0; mt<MT; mt++){
        #pragma unroll
        for (int i=0; i<2; i++){
            int row = m0 + wm + mt*16 + g + i*8;
            #pragma unroll
            for (int nt=0; nt<NTn; nt++){
                int col = n0 + wn + nt*8 + tg*2;
                float v0 = acc[mt][nt][i*2+0];
                float v1 = acc[mt][nt][i*2+1];
                if (bias){ v0 += bias[col]; v1 += bias[col+1]; }
                if (DO_GELU){ v0 = geluf(v0); v1 = geluf(v1); }
                if (Rm){
                    float2 rr = *(const float2*)(Rm + (size_t)row*ldr + col);
                    v0 += rr.x; v1 += rr.y;
                }
                if (ROUND_OUT){ v0 = rndtf(v0); v1 = rndtf(v1); }
                *(float2*)(C + (size_t)row*ldc + col) = make_float2(v0, v1);
            }
        }
    }
}

// ---------------- host-side launch helper ---------------------------------------
enum GMode { G_PLAIN, G_ROUND, G_GELU_ROUND };
static void gemm_main(const float*A,int lda, const float*B,int ldb,
                      float*C,int ldc, int M,int N,int K,
                      const float*bias,const float*R,int ldr, GMode mode)
{
    dim3 gr(N/128, M/128, 1);
    switch (mode){
    case G_PLAIN:
        gemm_tf32<false,false><<<gr,256,GEMM_SMEM>>>(A,lda,B,ldb,C,ldc,M,N,K,bias,R,ldr); break;
    case G_ROUND:
        gemm_tf32<false,true ><<<gr,256,GEMM_SMEM>>>(A,lda,B,ldb,C,ldc,M,N,K,bias,R,ldr); break;
    case G_GELU_ROUND:
        gemm_tf32<true ,true ><<<gr,256,GEMM_SMEM>>>(A,lda,B,ldb,C,ldc,M,N,K,bias,R,ldr); break;
    }
}

extern "C" void kernel_launch(void* const* d_in, const int* in_sizes, int n_in,
                              void* d_out, int out_size)
{
    (void)in_sizes; (void)n_in; (void)out_size;
    const float* x   = (const float*)d_in[0];
    const float* wq  = (const float*)d_in[1];
    const float* wk  = (const float*)d_in[2];
    const float* wv  = (const float*)d_in[3];
    const float* wo  = (const float*)d_in[4];
    const float* bo  = (const float*)d_in[5];
    const float* l1g = (const float*)d_in[6];
    const float* l1b = (const float*)d_in[7];
    const float* l2g = (const float*)d_in[8];
    const float* l2b = (const float*)d_in[9];
    const float* w1  = (const float*)d_in[10];
    const float* b1  = (const float*)d_in[11];
    const float* w2  = (const float*)d_in[12];
    const float* b2  = (const float*)d_in[13];
    float* out = (float*)d_out;

    void* p;
    float *y,*q,*k,*v,*o,*h,*a,*tmid;
    float *rwq,*rwk,*rwv,*rwo,*rw1,*rw2;
    cudaGetSymbolAddress(&p, g_y ); y    = (float*)p;
    cudaGetSymbolAddress(&p, g_q ); q    = (float*)p;
    cudaGetSymbolAddress(&p, g_k ); k    = (float*)p;
    cudaGetSymbolAddress(&p, g_v ); v    = (float*)p;
    cudaGetSymbolAddress(&p, g_o ); o    = (float*)p;
    cudaGetSymbolAddress(&p, g_h ); h    = (float*)p;
    cudaGetSymbolAddress(&p, g_a ); a    = (float*)p;
    cudaGetSymbolAddress(&p, g_t ); tmid = (float*)p;
    cudaGetSymbolAddress(&p, g_wq); rwq  = (float*)p;
    cudaGetSymbolAddress(&p, g_wk); rwk  = (float*)p;
    cudaGetSymbolAddress(&p, g_wv); rwv  = (float*)p;
    cudaGetSymbolAddress(&p, g_wo); rwo  = (float*)p;
    cudaGetSymbolAddress(&p, g_w1); rw1  = (float*)p;
    cudaGetSymbolAddress(&p, g_w2); rw2  = (float*)p;

    cudaFuncSetAttribute((const void*)flash_kernel,
                         cudaFuncAttributeMaxDynamicSharedMemorySize, FLASH_SMEM);
    cudaFuncSetAttribute((const void*)gemm_tf32<false,false>,
                         cudaFuncAttributeMaxDynamicSharedMemorySize, GEMM_SMEM);
    cudaFuncSetAttribute((const void*)gemm_tf32<false,true>,
                         cudaFuncAttributeMaxDynamicSharedMemorySize, GEMM_SMEM);
    cudaFuncSetAttribute((const void*)gemm_tf32<true,true>,
                         cudaFuncAttributeMaxDynamicSharedMemorySize, GEMM_SMEM);

    // round weights to tf32 once per call
    {
        int n4d = Dd*Dd/4, n4f = Dd*Ff/4, thr = 256;
        round_kernel<<<(n4d+thr-1)/thr,thr>>>(wq, rwq, n4d);
        round_kernel<<<(n4d+thr-1)/thr,thr>>>(wk, rwk, n4d);
        round_kernel<<<(n4d+thr-1)/thr,thr>>>(wv, rwv, n4d);
        round_kernel<<<(n4d+thr-1)/thr,thr>>>(wo, rwo, n4d);
        round_kernel<<<(n4f+thr-1)/thr,thr>>>(w1, rw1, n4f);
        round_kernel<<<(n4f+thr-1)/thr,thr>>>(w2, rw2, n4f);
    }

    for (int pass=0; pass<2; pass++){
        const float* lnin = pass ? h   : x;
        const float* gg   = pass ? l2g : l1g;
        const float* bbv  = pass ? l2b : l1b;
        ln_kernel<<<NTOK,256>>>(lnin, gg, bbv, y);
        gemm_main(y,Dd, rwq,Dd, q,Dd, NTOK,Dd,Dd, nullptr,nullptr,0, G_PLAIN);
        gemm_main(y,Dd, rwk,Dd, k,Dd, NTOK,Dd,Dd, nullptr,nullptr,0, G_PLAIN);
        gemm_main(y,Dd, rwv,Dd, v,Dd, NTOK,Dd,Dd, nullptr,nullptr,0, G_PLAIN);
        flash_kernel<<<dim3(16,32),256,FLASH_SMEM>>>(q, k, v, o);
        if (pass == 0)
            gemm_main(o,Dd, rwo,Dd, h,Dd, NTOK,Dd,Dd, bo, x, Dd, G_PLAIN);
        else
            gemm_main(o,Dd, rwo,Dd, a,Dd, NTOK,Dd,Dd, bo, nullptr,0, G_ROUND);
    }
    // FFN: t = gelu(a@w1 + b1) [rounded];  out = t@w2 + b2 + h  [exact]
    gemm_main(a   ,Dd, rw1,Ff, tmid,Ff, NTOK,Ff,Dd, b1, nullptr,0, G_GELU_ROUND);
    gemm_main(tmid,Ff, rw2,Dd, out ,Dd, NTOK,Dd,Ff, b2, h, Dd,     G_PLAIN);
}

// round 9
// speedup vs baseline: 2.3611x; 1.3213x over previous
#include <cuda_runtime.h>
#include <cuda_bf16.h>
#include <math.h>

#define Bb   2
#define Ss   2048
#define Dd   1024
#define Hh   16
#define HDd  64
#define Ff   4096
#define NTOK (Bb*Ss)   // 4096

// ---------------- scratch (device globals) --------------------------------------
__device__ __nv_bfloat16 gb_y[NTOK*Dd];         // LN output (bf16)
__device__ float g_q [NTOK*Dd];                 // fp32 (flash inputs)
__device__ float g_k [NTOK*Dd];
__device__ float g_v [NTOK*Dd];
__device__ __nv_bfloat16 gb_o[NTOK*Dd];         // attention out (bf16)
__device__ float g_h [NTOK*Dd];                 // residual stream (exact f32)
__device__ __nv_bfloat16 gb_a[NTOK*Dd];         // attn-2 proj out (bf16)
__device__ __nv_bfloat16 gb_t[NTOK*Ff];         // FFN mid (bf16)
// bf16 TRANSPOSED weight copies: W^T[n][k]
__device__ __nv_bfloat16 gb_wq[Dd*Dd], gb_wk[Dd*Dd], gb_wv[Dd*Dd], gb_wo[Dd*Dd];
__device__ __nv_bfloat16 gb_w1[Ff*Dd], gb_w2[Dd*Ff];

// ---------------- helpers -------------------------------------------------------
__device__ __forceinline__ unsigned f2tf(float x){
    unsigned u; asm("cvt.rna.tf32.f32 %0, %1;" : "=r"(u) : "f"(x)); return u;
}
__device__ __forceinline__ float rndtf(float x){ return __uint_as_float(f2tf(x)); }
__device__ __forceinline__ float geluf(float x){
    return 0.5f * x * (1.0f + erff(x * 0.70710678118654752f));
}
__device__ __forceinline__ void mma8(float* c, const unsigned* a, unsigned b0, unsigned b1){
    asm volatile(
        "mma.sync.aligned.m16n8k8.row.col.f32.tf32.tf32.f32 "
        "{%0,%1,%2,%3}, {%4,%5,%6,%7}, {%8,%9}, {%0,%1,%2,%3};"
        : "+f"(c[0]), "+f"(c[1]), "+f"(c[2]), "+f"(c[3])
        : "r"(a[0]), "r"(a[1]), "r"(a[2]), "r"(a[3]), "r"(b0), "r"(b1));
}
__device__ __forceinline__ void mma16bf(float* c, const unsigned* a, unsigned b0, unsigned b1){
    asm volatile(
        "mma.sync.aligned.m16n8k16.row.col.f32.bf16.bf16.f32 "
        "{%0,%1,%2,%3}, {%4,%5,%6,%7}, {%8,%9}, {%0,%1,%2,%3};"
        : "+f"(c[0]), "+f"(c[1]), "+f"(c[2]), "+f"(c[3])
        : "r"(a[0]), "r"(a[1]), "r"(a[2]), "r"(a[3]), "r"(b0), "r"(b1));
}
__device__ __forceinline__ void cpa16(void* dst, const void* src){
    unsigned d = (unsigned)__cvta_generic_to_shared(dst);
    asm volatile("cp.async.cg.shared.global [%0], [%1], 16;" :: "r"(d), "l"(src));
}
__device__ __forceinline__ void cp_commit(){ asm volatile("cp.async.commit_group;"); }
template<int N> __device__ __forceinline__ void cp_wait(){
    asm volatile("cp.async.wait_group %0;" :: "n"(N));
}

// ---------------- weight transpose-convert: f32 [K][N] -> bf16 [N][K] ------------
__global__ void transpose_bf16_kernel(const float* __restrict__ in,
                                      __nv_bfloat16* __restrict__ out,
                                      int K, int N)
{
    __shared__ float tile[32][33];
    int k0 = blockIdx.y*32, n0 = blockIdx.x*32;
    int tx = threadIdx.x, ty = threadIdx.y;
    #pragma unroll
    for (int j=0;j<4;j++)
        tile[ty+8*j][tx] = in[(size_t)(k0+ty+8*j)*N + n0 + tx];
    __syncthreads();
    #pragma unroll
    for (int j=0;j<4;j++)
        out[(size_t)(n0+ty+8*j)*K + k0 + tx] = __float2bfloat16_rn(tile[tx][ty+8*j]);
}

// ---------------- LayerNorm (bf16 output) ---------------------------------------
__global__ void ln_kernel(const float* __restrict__ x,
                          const float* __restrict__ gam,
                          const float* __restrict__ bet,
                          __nv_bfloat16* __restrict__ y)
{
    __shared__ float rs[2][8];
    int row = blockIdx.x, t = threadIdx.x;
    float4 v = ((const float4*)(x + (size_t)row*Dd))[t];
    float s = v.x+v.y+v.z+v.w;
    float q = v.x*v.x+v.y*v.y+v.z*v.z+v.w*v.w;
    #pragma unroll
    for (int o=16;o;o>>=1){ s += __shfl_xor_sync(0xffffffffu,s,o);
                            q += __shfl_xor_sync(0xffffffffu,q,o); }
    if ((t&31)==0){ rs[0][t>>5]=s; rs[1][t>>5]=q; }
    __syncthreads();
    float S=0.f,Q=0.f;
    #pragma unroll
    for (int i=0;i<8;i++){ S+=rs[0][i]; Q+=rs[1][i]; }
    float mu = S*(1.0f/Dd);
    float var = Q*(1.0f/Dd) - mu*mu;
    float rstd = rsqrtf(var + 1e-5f);
    float4 g4 = ((const float4*)gam)[t];
    float4 b4 = ((const float4*)bet)[t];
    __nv_bfloat162 p0, p1;
    p0.x = __float2bfloat16_rn((v.x-mu)*rstd*g4.x + b4.x);
    p0.y = __float2bfloat16_rn((v.y-mu)*rstd*g4.y + b4.y);
    p1.x = __float2bfloat16_rn((v.z-mu)*rstd*g4.z + b4.z);
    p1.y = __float2bfloat16_rn((v.w-mu)*rstd*g4.w + b4.w);
    __nv_bfloat162* yp = (__nv_bfloat162*)(y + (size_t)row*Dd + t*4);
    yp[0] = p0; yp[1] = p1;
}

// ---------------- flash attention (tf32 mma, online softmax, bf16 output) -------
#define QS_LD 68
#define VS_LD 72
#define PS_LD 132
#define FLASH_SMEM ((128*QS_LD*2 + 128*VS_LD + 128*PS_LD) * 4)

__global__ __launch_bounds__(256,1)
void flash_kernel(const float* __restrict__ Q, const float* __restrict__ K,
                  const float* __restrict__ V, __nv_bfloat16* __restrict__ O)
{
    extern __shared__ float sm[];
    float* Qs = sm;
    float* Ks = Qs + 128*QS_LD;
    float* Vs = Ks + 128*QS_LD;
    float* Ps = Vs + 128*VS_LD;

    int qt = 15 - blockIdx.x;
    int z = blockIdx.y, zb = z >> 4, zh = z & 15;
    const float* Qp = Q + (size_t)zb*Ss*Dd + zh*HDd;
    const float* Kp = K + (size_t)zb*Ss*Dd + zh*HDd;
    const float* Vp = V + (size_t)zb*Ss*Dd + zh*HDd;
    __nv_bfloat16* Op = O + (size_t)zb*Ss*Dd + zh*HDd;

    int tid = threadIdx.x, warp = tid>>5, lane = tid&31;
    int g = lane>>2, tg = lane&3;
    int q0 = qt*128;

    #pragma unroll
    for (int i=0;i<8;i++){
        int idx = tid + i*256;
        int r = idx>>4, c4 = idx&15;
        float4 v4 = *(const float4*)(Qp + (size_t)(q0+r)*Dd + c4*4);
        float4 cv;
        cv.x=rndtf(v4.x); cv.y=rndtf(v4.y); cv.z=rndtf(v4.z); cv.w=rndtf(v4.w);
        *(float4*)&Qs[r*QS_LD + c4*4] = cv;
    }
    __syncthreads();

    unsigned qf[8][4];
    int pr0 = warp*16 + g;
    #pragma unroll
    for (int kc=0;kc<8;kc++){
        qf[kc][0] = __float_as_uint(Qs[ pr0   *QS_LD + kc*8+tg  ]);
        qf[kc][1] = __float_as_uint(Qs[(pr0+8)*QS_LD + kc*8+tg  ]);
        qf[kc][2] = __float_as_uint(Qs[ pr0   *QS_LD + kc*8+tg+4]);
        qf[kc][3] = __float_as_uint(Qs[(pr0+8)*QS_LD + kc*8+tg+4]);
    }

    float oa[8][4];
    #pragma unroll
    for (int i=0;i<8;i++){ oa[i][0]=0.f;oa[i][1]=0.f;oa[i][2]=0.f;oa[i][3]=0.f; }
    float m0=-1e30f, m1=-1e30f, l0=0.f, l1=0.f;
    int grow0 = q0 + pr0, grow1 = grow0 + 8;

    int kt0 = (qt==15) ? 0 : qt;
    for (int kt=kt0; kt<16; kt++){
        __syncthreads();
        #pragma unroll
        for (int i=0;i<8;i++){
            int idx = tid + i*256;
            int r = idx>>4, c4 = idx&15;
            float4 kv = *(const float4*)(Kp + (size_t)(kt*128+r)*Dd + c4*4);
            float4 ck;
            ck.x=rndtf(kv.x); ck.y=rndtf(kv.y); ck.z=rndtf(kv.z); ck.w=rndtf(kv.w);
            *(float4*)&Ks[r*QS_LD + c4*4] = ck;
            float4 vv = *(const float4*)(Vp + (size_t)(kt*128+r)*Dd + c4*4);
            float4 cv;
            cv.x=rndtf(vv.x); cv.y=rndtf(vv.y); cv.z=rndtf(vv.z); cv.w=rndtf(vv.w);
            *(float4*)&Vs[r*VS_LD + c4*4] = cv;
        }
        __syncthreads();

        float sc[16][4];
        #pragma unroll
        for (int nt=0;nt<16;nt++){ sc[nt][0]=0.f;sc[nt][1]=0.f;sc[nt][2]=0.f;sc[nt][3]=0.f; }
        #pragma unroll
        for (int kc=0;kc<8;kc++){
            #pragma unroll
            for (int nt=0;nt<16;nt++){
                unsigned b0 = __float_as_uint(Ks[(nt*8+g)*QS_LD + kc*8+tg  ]);
                unsigned b1 = __float_as_uint(Ks[(nt*8+g)*QS_LD + kc*8+tg+4]);
                mma8(sc[nt], qf[kc], b0, b1);
            }
        }

        float tm0=-1e30f, tm1=-1e30f;
        #pragma unroll
        for (int nt=0;nt<16;nt++){
            #pragma unroll
            for (int j=0;j<4;j++){
                int gcol = kt*128 + nt*8 + tg*2 + (j&1);
                int grow = (j<2) ? grow0 : grow1;
                float s = (gcol<=grow) ? -1e9f : sc[nt][j]*0.125f;
                sc[nt][j] = s;
                if (j<2) tm0 = fmaxf(tm0,s); else tm1 = fmaxf(tm1,s);
            }
        }
        tm0 = fmaxf(tm0, __shfl_xor_sync(0xffffffffu,tm0,1));
        tm0 = fmaxf(tm0, __shfl_xor_sync(0xffffffffu,tm0,2));
        tm1 = fmaxf(tm1, __shfl_xor_sync(0xffffffffu,tm1,1));
        tm1 = fmaxf(tm1, __shfl_xor_sync(0xffffffffu,tm1,2));
        float mn0 = fmaxf(m0,tm0), mn1 = fmaxf(m1,tm1);
        float sf0 = __expf(m0-mn0), sf1 = __expf(m1-mn1);
        float rs0=0.f, rs1=0.f;
        #pragma unroll
        for (int nt=0;nt<16;nt++){
            sc[nt][0] = __expf(sc[nt][0]-mn0); rs0 += sc[nt][0];
            sc[nt][1] = __expf(sc[nt][1]-mn0); rs0 += sc[nt][1];
            sc[nt][2] = __expf(sc[nt][2]-mn1); rs1 += sc[nt][2];
            sc[nt][3] = __expf(sc[nt][3]-mn1); rs1 += sc[nt][3];
        }
        rs0 += __shfl_xor_sync(0xffffffffu,rs0,1);
        rs0 += __shfl_xor_sync(0xffffffffu,rs0,2);
        rs1 += __shfl_xor_sync(0xffffffffu,rs1,1);
        rs1 += __shfl_xor_sync(0xffffffffu,rs1,2);
        l0 = l0*sf0 + rs0;  l1 = l1*sf1 + rs1;
        m0 = mn0;  m1 = mn1;
        #pragma unroll
        for (int i=0;i<8;i++){
            oa[i][0]*=sf0; oa[i][1]*=sf0; oa[i][2]*=sf1; oa[i][3]*=sf1;
        }

        #pragma unroll
        for (int nt=0;nt<16;nt++){
            float2 pa, pb;
            pa.x = rndtf(sc[nt][0]); pa.y = rndtf(sc[nt][1]);
            pb.x = rndtf(sc[nt][2]); pb.y = rndtf(sc[nt][3]);
            *(float2*)&Ps[ pr0   *PS_LD + nt*8 + tg*2] = pa;
            *(float2*)&Ps[(pr0+8)*PS_LD + nt*8 + tg*2] = pb;
        }
        __syncwarp();
        #pragma unroll
        for (int kc2=0;kc2<16;kc2++){
            unsigned pf[4];
            pf[0] = __float_as_uint(Ps[ pr0   *PS_LD + kc2*8+tg  ]);
            pf[1] = __float_as_uint(Ps[(pr0+8)*PS_LD + kc2*8+tg  ]);
            pf[2] = __float_as_uint(Ps[ pr0   *PS_LD + kc2*8+tg+4]);
            pf[3] = __float_as_uint(Ps[(pr0+8)*PS_LD + kc2*8+tg+4]);
            #pragma unroll
            for (int nt2=0;nt2<8;nt2++){
                unsigned b0 = __float_as_uint(Vs[(kc2*8+tg  )*VS_LD + nt2*8+g]);
                unsigned b1 = __float_as_uint(Vs[(kc2*8+tg+4)*VS_LD + nt2*8+g]);
                mma8(oa[nt2], pf, b0, b1);
            }
        }
    }

    // bf16 output (feeds O-projection GEMM as A)
    float inv0 = 1.f/l0, inv1 = 1.f/l1;
    #pragma unroll
    for (int nt2=0;nt2<8;nt2++){
        __nv_bfloat162 w0, w1;
        w0.x = __float2bfloat16_rn(oa[nt2][0]*inv0);
        w0.y = __float2bfloat16_rn(oa[nt2][1]*inv0);
        w1.x = __float2bfloat16_rn(oa[nt2][2]*inv1);
        w1.y = __float2bfloat16_rn(oa[nt2][3]*inv1);
        *(__nv_bfloat162*)(Op + (size_t)grow0*Dd + nt2*8 + tg*2) = w0;
        *(__nv_bfloat162*)(Op + (size_t)grow1*Dd + nt2*8 + tg*2) = w1;
    }
}

// ---------------- pipelined bf16 GEMM (cp.async double-buffered) -----------------
// C[M,N] = A[M,K](bf16) @ B[K,N], where B is given TRANSPOSED bf16: BT[n][k].
// mma.sync.m16n8k16 bf16, fp32 accum. SMEM stride 72 halfs (36 words = 4 mod 32):
// all fragment LDS.32 conflict-free.
#define BKg  64
#define ALD  72                       // halfs per smem row
#define ASTG (128*ALD)                // halfs per stage (A and B identical)
#define GEMM_SMEM (4*ASTG*2)          // 73728 bytes

template<bool DO_GELU, bool OUT_BF16>
__global__ __launch_bounds__(256,2)
void gemm_bf16(const __nv_bfloat16* __restrict__ A, int lda,
               const __nv_bfloat16* __restrict__ BT, int ldb,
               void* __restrict__ Cv, int ldc,
               int M, int N, int K,
               const float* __restrict__ bias,
               const float* __restrict__ Rm, int ldr)
{
    constexpr int MT = 4, NTn = 4;            // 64x32 warp tile
    extern __shared__ __nv_bfloat16 hsm[];

    int m0 = blockIdx.y*128, n0 = blockIdx.x*128;
    int tid = threadIdx.x, warp = tid>>5, lane = tid&31;
    int wm = (warp>>2)*64, wn = (warp&3)*32;
    int g = lane>>2, tg = lane&3;

    int cr = tid>>3, cch = (tid&7)*8;         // copy: row base, col offset (halfs)
    const __nv_bfloat16* Ap = A  + (size_t)(m0+cr)*lda + cch;
    const __nv_bfloat16* Bp = BT + (size_t)(n0+cr)*ldb + cch;

    float acc[MT][NTn][4];
    #pragma unroll
    for (int i=0;i<MT;i++)
        #pragma unroll
        for (int j=0;j<NTn;j++)
            #pragma unroll
            for (int r=0;r<4;r++) acc[i][j][r]=0.f;

    auto issue = [&](int k0, int s){
        __nv_bfloat16* As = hsm + s*ASTG;
        __nv_bfloat16* Bs = hsm + 2*ASTG + s*ASTG;
        #pragma unroll
        for (int i=0;i<4;i++)
            cpa16(&As[(cr+32*i)*ALD + cch], Ap + (size_t)(32*i)*lda + k0);
        #pragma unroll
        for (int i=0;i<4;i++)
            cpa16(&Bs[(cr+32*i)*ALD + cch], Bp + (size_t)(32*i)*ldb + k0);
        cp_commit();
    };

    int nk = K/BKg;
    issue(0, 0);
    for (int it=0; it<nk; it++){
        int s = it&1;
        if (it+1 < nk) issue((it+1)*BKg, s^1);
        if (it+1 < nk) cp_wait<1>(); else cp_wait<0>();
        __syncthreads();

        const __nv_bfloat16* As = hsm + s*ASTG;
        const __nv_bfloat16* Bs = hsm + 2*ASTG + s*ASTG;
        #pragma unroll
        for (int ks=0; ks<BKg/16; ks++){
            int kk = ks*16 + 2*tg;
            unsigned af[MT][4], bf[NTn][2];
            #pragma unroll
            for (int mt=0; mt<MT; mt++){
                const __nv_bfloat16* ap = As + (wm + mt*16 + g)*ALD + kk;
                af[mt][0] = *(const unsigned*)(ap);
                af[mt][1] = *(const unsigned*)(ap + 8*ALD);
                af[mt][2] = *(const unsigned*)(ap + 8);
                af[mt][3] = *(const unsigned*)(ap + 8*ALD + 8);
            }
            #pragma unroll
            for (int nt=0; nt<NTn; nt++){
                const __nv_bfloat16* bp = Bs + (wn + nt*8 + g)*ALD + kk;
                bf[nt][0] = *(const unsigned*)(bp);
                bf[nt][1] = *(const unsigned*)(bp + 8);
            }
            #pragma unroll
            for (int mt=0; mt<MT; mt++)
                #pragma unroll
                for (int nt=0; nt<NTn; nt++)
                    mma16bf(acc[mt][nt], af[mt], bf[nt][0], bf[nt][1]);
        }
        __syncthreads();
    }

    #pragma unroll
    for (int mt=0; mt<MT; mt++){
        #pragma unroll
        for (int i=0; i<2; i++){
            int row = m0 + wm + mt*16 + g + i*8;
            #pragma unroll
            for (int nt=0; nt<NTn; nt++){
                int col = n0 + wn + nt*8 + tg*2;
                float v0 = acc[mt][nt][i*2+0];
                float v1 = acc[mt][nt][i*2+1];
                if (bias){ v0 += bias[col]; v1 += bias[col+1]; }
                if (DO_GELU){ v0 = geluf(v0); v1 = geluf(v1); }
                if (Rm){
                    float2 rr = *(const float2*)(Rm + (size_t)row*ldr + col);
                    v0 += rr.x; v1 += rr.y;
                }
                if (OUT_BF16){
                    __nv_bfloat162 w;
                    w.x = __float2bfloat16_rn(v0);
                    w.y = __float2bfloat16_rn(v1);
                    *(__nv_bfloat162*)((__nv_bfloat16*)Cv + (size_t)row*ldc + col) = w;
                }else{
                    *(float2*)((float*)Cv + (size_t)row*ldc + col) = make_float2(v0, v1);
                }
            }
        }
    }
}

// ---------------- host-side launch helper ---------------------------------------
enum GMode { G_F32, G_BF16, G_GELU_BF16 };
static void gemm_run(const __nv_bfloat16*A,int lda, const __nv_bfloat16*BT,int ldb,
                     void*C,int ldc, int M,int N,int K,
                     const float*bias,const float*R,int ldr, GMode mode)
{
    dim3 gr(N/128, M/128, 1);
    switch (mode){
    case G_F32:
        gemm_bf16<false,false><<<gr,256,GEMM_SMEM>>>(A,lda,BT,ldb,C,ldc,M,N,K,bias,R,ldr); break;
    case G_BF16:
        gemm_bf16<false,true ><<<gr,256,GEMM_SMEM>>>(A,lda,BT,ldb,C,ldc,M,N,K,bias,R,ldr); break;
    case G_GELU_BF16:
        gemm_bf16<true ,true ><<<gr,256,GEMM_SMEM>>>(A,lda,BT,ldb,C,ldc,M,N,K,bias,R,ldr); break;
    }
}

extern "C" void kernel_launch(void* const* d_in, const int* in_sizes, int n_in,
                              void* d_out, int out_size)
{
    (void)in_sizes; (void)n_in; (void)out_size;
    const float* x   = (const float*)d_in[0];
    const float* wq  = (const float*)d_in[1];
    const float* wk  = (const float*)d_in[2];
    const float* wv  = (const float*)d_in[3];
    const float* wo  = (const float*)d_in[4];
    const float* bo  = (const float*)d_in[5];
    const float* l1g = (const float*)d_in[6];
    const float* l1b = (const float*)d_in[7];
    const float* l2g = (const float*)d_in[8];
    const float* l2b = (const float*)d_in[9];
    const float* w1  = (const float*)d_in[10];
    const float* b1  = (const float*)d_in[11];
    const float* w2  = (const float*)d_in[12];
    const float* b2  = (const float*)d_in[13];
    float* out = (float*)d_out;

    void* p;
    __nv_bfloat16 *y,*o,*a,*tmid,*twq,*twk,*twv,*two,*tw1,*tw2;
    float *q,*k,*v,*h;
    cudaGetSymbolAddress(&p, gb_y ); y    = (__nv_bfloat16*)p;
    cudaGetSymbolAddress(&p, g_q  ); q    = (float*)p;
    cudaGetSymbolAddress(&p, g_k  ); k    = (float*)p;
    cudaGetSymbolAddress(&p, g_v  ); v    = (float*)p;
    cudaGetSymbolAddress(&p, gb_o ); o    = (__nv_bfloat16*)p;
    cudaGetSymbolAddress(&p, g_h  ); h    = (float*)p;
    cudaGetSymbolAddress(&p, gb_a ); a    = (__nv_bfloat16*)p;
    cudaGetSymbolAddress(&p, gb_t ); tmid = (__nv_bfloat16*)p;
    cudaGetSymbolAddress(&p, gb_wq); twq  = (__nv_bfloat16*)p;
    cudaGetSymbolAddress(&p, gb_wk); twk  = (__nv_bfloat16*)p;
    cudaGetSymbolAddress(&p, gb_wv); twv  = (__nv_bfloat16*)p;
    cudaGetSymbolAddress(&p, gb_wo); two  = (__nv_bfloat16*)p;
    cudaGetSymbolAddress(&p, gb_w1); tw1  = (__nv_bfloat16*)p;
    cudaGetSymbolAddress(&p, gb_w2); tw2  = (__nv_bfloat16*)p;

    cudaFuncSetAttribute((const void*)flash_kernel,
                         cudaFuncAttributeMaxDynamicSharedMemorySize, FLASH_SMEM);
    cudaFuncSetAttribute((const void*)gemm_bf16<false,false>,
                         cudaFuncAttributeMaxDynamicSharedMemorySize, GEMM_SMEM);
    cudaFuncSetAttribute((const void*)gemm_bf16<false,true>,
                         cudaFuncAttributeMaxDynamicSharedMemorySize, GEMM_SMEM);
    cudaFuncSetAttribute((const void*)gemm_bf16<true,true>,
                         cudaFuncAttributeMaxDynamicSharedMemorySize, GEMM_SMEM);

    // weights -> transposed bf16 copies (W^T[n][k])
    {
        dim3 tb(32,8);
        transpose_bf16_kernel<<<dim3(Dd/32,Dd/32),tb>>>(wq, twq, Dd, Dd);
        transpose_bf16_kernel<<<dim3(Dd/32,Dd/32),tb>>>(wk, twk, Dd, Dd);
        transpose_bf16_kernel<<<dim3(Dd/32,Dd/32),tb>>>(wv, twv, Dd, Dd);
        transpose_bf16_kernel<<<dim3(Dd/32,Dd/32),tb>>>(wo, two, Dd, Dd);
        transpose_bf16_kernel<<<dim3(Ff/32,Dd/32),tb>>>(w1, tw1, Dd, Ff);
        transpose_bf16_kernel<<<dim3(Dd/32,Ff/32),tb>>>(w2, tw2, Ff, Dd);
    }

    for (int pass=0; pass<2; pass++){
        const float* lnin = pass ? h   : x;
        const float* gg   = pass ? l2g : l1g;
        const float* bbv  = pass ? l2b : l1b;
        ln_kernel<<<NTOK,256>>>(lnin, gg, bbv, y);
        gemm_run(y,Dd, twq,Dd, q,Dd, NTOK,Dd,Dd, nullptr,nullptr,0, G_F32);
        gemm_run(y,Dd, twk,Dd, k,Dd, NTOK,Dd,Dd, nullptr,nullptr,0, G_F32);
        gemm_run(y,Dd, twv,Dd, v,Dd, NTOK,Dd,Dd, nullptr,nullptr,0, G_F32);
        flash_kernel<<<dim3(16,32),256,FLASH_SMEM>>>(q, k, v, o);
        if (pass == 0)
            gemm_run(o,Dd, two,Dd, h,Dd, NTOK,Dd,Dd, bo, x, Dd, G_F32);
        else
            gemm_run(o,Dd, two,Dd, a,Dd, NTOK,Dd,Dd, bo, nullptr,0, G_BF16);
    }
    // FFN: t = gelu(a@w1 + b1) [bf16];  out = t@w2 + b2 + h  [f32]
    gemm_run(a   ,Dd, tw1,Dd, tmid,Ff, NTOK,Ff,Dd, b1, nullptr,0, G_GELU_BF16);
    gemm_run(tmid,Ff, tw2,Ff, out ,Dd, NTOK,Dd,Ff, b2, h, Dd,     G_F32);
}